// round 3
// baseline (speedup 1.0000x reference)
#include <cuda_runtime.h>
#include <math.h>

#define NN   50000
#define EE   150000
#define GG   200
#define DD   320
#define EDIN 15
#define EHH  32
#define NBB  3
#define NTT  9

// ---------------- scratch (static device globals; allocation-free) ----------------
__device__ float g_NEA[NTT * EE * EHH];   // per-type edge MLP output [9,150000,32]
__device__ float g_XS[NN * EHH];          // x @ W1[0:320]
__device__ float g_XD[NN * EHH];          // x @ W1[320:640]
__device__ float g_Q[NN * DD];
__device__ float g_K[NN * DD];
__device__ float g_V[NN * DD];
__device__ float g_EB[EE * DD];           // edge projection e = nea @ We + be
__device__ float g_ACC[NN * DD];
__device__ float g_H[NN * DD];
__device__ float g_AL[EE];                // alpha, reused as exp(alpha - amax)
__device__ float g_AMAX[NN];
__device__ float g_DEN[NN];
__device__ float g_GS[GG];
__device__ float g_GQ[GG];
__device__ int   g_GC[GG];
__device__ float g_MEAN[GG];
__device__ float g_RSTD[GG];
__device__ unsigned g_OUTU[GG * DD];

// ---------------- generic tiled SGEMM: C[MxNout] = A[MxK] @ B[KxNout](ldb) (+bias) (+=C) ----
// TM=128, TN=64, TK=16, 256 threads, 8x4 microtile. K must be a multiple of 16,
// Nout a multiple of 4 (true for all call sites: K in {320,32}, Nout in {320,32}).
template<bool ACCUM>
__global__ void __launch_bounds__(256) sgemm(
    const float* __restrict__ A, const float* __restrict__ B,
    const float* __restrict__ bias, float* __restrict__ C,
    int M, int K, int Nout, int ldb)
{
    __shared__ __align__(16) float As[16][132];   // transposed: As[k][row]
    __shared__ __align__(16) float Bs[16][64];

    int tid = threadIdx.x;
    int tx = tid & 15, ty = tid >> 4;
    int m0 = blockIdx.y * 128, n0 = blockIdx.x * 64;

    float acc[8][4];
#pragma unroll
    for (int i = 0; i < 8; i++)
#pragma unroll
        for (int j = 0; j < 4; j++) acc[i][j] = 0.f;

    int ar = tid >> 2;            // 0..63
    int ac = (tid & 3) * 4;       // 0,4,8,12
    int bk = tid >> 4;            // 0..15
    int bc = (tid & 15) * 4;      // 0..60

    for (int k0 = 0; k0 < K; k0 += 16) {
#pragma unroll
        for (int rr = 0; rr < 2; rr++) {
            int row = m0 + ar + rr * 64;
            float4 av = make_float4(0.f, 0.f, 0.f, 0.f);
            if (row < M) av = *(const float4*)(A + (size_t)row * K + k0 + ac);
            As[ac + 0][ar + rr * 64] = av.x;
            As[ac + 1][ar + rr * 64] = av.y;
            As[ac + 2][ar + rr * 64] = av.z;
            As[ac + 3][ar + rr * 64] = av.w;
        }
        {
            float4 bv = make_float4(0.f, 0.f, 0.f, 0.f);
            if (n0 + bc < Nout)
                bv = *(const float4*)(B + (size_t)(k0 + bk) * ldb + n0 + bc);
            *(float4*)&Bs[bk][bc] = bv;
        }
        __syncthreads();
#pragma unroll
        for (int k = 0; k < 16; k++) {
            float a[8], b[4];
            *(float4*)(a)     = *(const float4*)&As[k][ty * 8];
            *(float4*)(a + 4) = *(const float4*)&As[k][ty * 8 + 4];
            *(float4*)(b)     = *(const float4*)&Bs[k][tx * 4];
#pragma unroll
            for (int i = 0; i < 8; i++)
#pragma unroll
                for (int j = 0; j < 4; j++)
                    acc[i][j] += a[i] * b[j];
        }
        __syncthreads();
    }

#pragma unroll
    for (int i = 0; i < 8; i++) {
        int row = m0 + ty * 8 + i;
        if (row >= M) continue;
#pragma unroll
        for (int j = 0; j < 4; j++) {
            int col = n0 + tx * 4 + j;
            if (col >= Nout) continue;
            float v = acc[i][j];
            if (bias) v += bias[col];
            if (ACCUM) v += C[(size_t)row * Nout + col];
            C[(size_t)row * Nout + col] = v;
        }
    }
}

// ---------------- edge MLP: nea = (leaky(Xs[src]+Xd[dst]+ea@W1e+b1)) @ W2 + b2 ----------
__global__ void edge_mlp(const int* __restrict__ EI, const float* __restrict__ EA,
                         const float* __restrict__ W1, const float* __restrict__ b1,
                         const float* __restrict__ W2, const float* __restrict__ b2)
{
    __shared__ float sW1e[EDIN * EHH];
    __shared__ float sW2[EHH * EHH];
    __shared__ float sb1[EHH], sb2[EHH];
    int tid = threadIdx.x;
    for (int i = tid; i < EDIN * EHH; i += blockDim.x) sW1e[i] = W1[640 * EHH + i];
    for (int i = tid; i < EHH * EHH; i += blockDim.x)  sW2[i]  = W2[i];
    if (tid < EHH) { sb1[tid] = b1[tid]; sb2[tid] = b2[tid]; }
    __syncthreads();

    long w = (long)blockIdx.x * (blockDim.x / 32) + tid / 32;
    int lane = tid & 31;
    if (w >= (long)NTT * EE) return;
    int t = (int)(w / EE);
    int e = (int)(w % EE);
    int src = EI[((size_t)t * 2 + 0) * EE + e];
    int dst = EI[((size_t)t * 2 + 1) * EE + e];

    float eav = 0.f;
    if (lane < EDIN) eav = EA[((size_t)t * EE + e) * EDIN + lane];

    float h = sb1[lane] + g_XS[(size_t)src * EHH + lane] + g_XD[(size_t)dst * EHH + lane];
#pragma unroll
    for (int i = 0; i < EDIN; i++)
        h += __shfl_sync(0xffffffffu, eav, i) * sW1e[i * EHH + lane];
    h = h > 0.f ? h : 0.01f * h;

    float o = sb2[lane];
#pragma unroll
    for (int i = 0; i < EHH; i++)
        o += __shfl_sync(0xffffffffu, h, i) * sW2[i * EHH + lane];

    g_NEA[((size_t)t * EE + e) * EHH + lane] = o;
}

// ---------------- attention passes ----------------
__global__ void att_pass1(const int* __restrict__ srcI, const int* __restrict__ dstI)
{
    int w = blockIdx.x * (blockDim.x / 32) + threadIdx.x / 32;
    int lane = threadIdx.x & 31;
    if (w >= EE) return;
    int src = srcI[w], dst = dstI[w];
    const float* q  = g_Q  + (size_t)dst * DD;
    const float* kk = g_K  + (size_t)src * DD;
    const float* eb = g_EB + (size_t)w * DD;
    float s = 0.f;
#pragma unroll
    for (int c = lane; c < DD; c += 32)
        s += q[c] * (kk[c] + eb[c]);
#pragma unroll
    for (int off = 16; off; off >>= 1) s += __shfl_xor_sync(0xffffffffu, s, off);
    if (lane == 0) {
        float al = s * 0.05590169943749474f;  // 1/sqrt(320)
        g_AL[w] = al;
        if (al >= 0.f) atomicMax((int*)&g_AMAX[dst], __float_as_int(al));
        else           atomicMin((unsigned*)&g_AMAX[dst], __float_as_uint(al));
    }
}

__global__ void att_pass2(const int* __restrict__ dstI)
{
    int e = blockIdx.x * blockDim.x + threadIdx.x;
    if (e >= EE) return;
    int dst = dstI[e];
    float ex = expf(g_AL[e] - g_AMAX[dst]);
    g_AL[e] = ex;
    atomicAdd(&g_DEN[dst], ex);
}

__global__ void att_pass3(const int* __restrict__ srcI, const int* __restrict__ dstI)
{
    int w = blockIdx.x * (blockDim.x / 32) + threadIdx.x / 32;
    int lane = threadIdx.x & 31;
    if (w >= EE) return;
    int src = srcI[w], dst = dstI[w];
    float wgt = g_AL[w] / (g_DEN[dst] + 1e-16f);
    const float* v  = g_V  + (size_t)src * DD;
    const float* eb = g_EB + (size_t)w * DD;
    float* out = g_ACC + (size_t)dst * DD;
#pragma unroll
    for (int c = lane; c < DD; c += 32)
        atomicAdd(&out[c], wgt * (v[c] + eb[c]));
}

// ---------------- misc ----------------
__global__ void fillf(float* p, float v, int n)
{
    int i = blockIdx.x * blockDim.x + threadIdx.x;
    if (i < n) p[i] = v;
}

__global__ void count_nodes(const int* __restrict__ batch)
{
    int i = blockIdx.x * blockDim.x + threadIdx.x;
    if (i < NN) atomicAdd(&g_GC[batch[i]], 1);
}

__global__ void gstats(const int* __restrict__ batch)
{
    int w = blockIdx.x * (blockDim.x / 32) + threadIdx.x / 32;
    int lane = threadIdx.x & 31;
    if (w >= NN) return;
    const float* a = g_ACC + (size_t)w * DD;
    float s1 = 0.f, s2 = 0.f;
#pragma unroll
    for (int c = lane; c < DD; c += 32) {
        float v = a[c] * (1.f / 9.f);
        v = v > 0.f ? v : 0.01f * v;
        s1 += v; s2 += v * v;
    }
#pragma unroll
    for (int off = 16; off; off >>= 1) {
        s1 += __shfl_xor_sync(0xffffffffu, s1, off);
        s2 += __shfl_xor_sync(0xffffffffu, s2, off);
    }
    if (lane == 0) {
        int g = batch[w];
        atomicAdd(&g_GS[g], s1);
        atomicAdd(&g_GQ[g], s2);
    }
}

__global__ void gfinal()
{
    int g = blockIdx.x * blockDim.x + threadIdx.x;
    if (g >= GG) return;
    float cnt  = (float)g_GC[g];
    float norm = fmaxf(cnt, 1.f) * (float)DD;
    float mean = g_GS[g] / norm;
    float var  = fmaxf(g_GQ[g] / norm - mean * mean, 0.f);
    g_MEAN[g] = mean;
    g_RSTD[g] = rsqrtf(var + 1e-5f);
}

__global__ void hupdate(const int* __restrict__ batch,
                        const float* __restrict__ gamma, const float* __restrict__ beta)
{
    size_t i = (size_t)blockIdx.x * blockDim.x + threadIdx.x;
    if (i >= (size_t)NN * DD) return;
    int node = (int)(i / DD), c = (int)(i % DD);
    int g = batch[node];
    float v = g_ACC[i] * (1.f / 9.f);
    v = v > 0.f ? v : 0.01f * v;
    float xn = (v - g_MEAN[g]) * g_RSTD[g] * gamma[c] + beta[c];
    g_H[i] = 0.5f * (g_H[i] + xn);
}

__device__ __forceinline__ unsigned fkey(float f)
{
    unsigned u = __float_as_uint(f);
    return (u & 0x80000000u) ? ~u : (u | 0x80000000u);
}
__device__ __forceinline__ float funkey(unsigned u)
{
    return (u & 0x80000000u) ? __uint_as_float(u & 0x7FFFFFFFu) : __uint_as_float(~u);
}

__global__ void maxred(const int* __restrict__ batch)
{
    size_t i = (size_t)blockIdx.x * blockDim.x + threadIdx.x;
    if (i >= (size_t)NN * DD) return;
    int node = (int)(i / DD), c = (int)(i % DD);
    atomicMax(&g_OUTU[(size_t)batch[node] * DD + c], fkey(g_H[i]));
}

__global__ void finalize(float* __restrict__ out)
{
    int i = blockIdx.x * blockDim.x + threadIdx.x;
    if (i < GG * DD) out[i] = funkey(g_OUTU[i]);
}

// ---------------- host orchestration ----------------
extern "C" void kernel_launch(void* const* d_in, const int* in_sizes, int n_in,
                              void* d_out, int out_size)
{
    const float* x     = (const float*)d_in[0];
    const int*   batch = (const int*)d_in[1];
    const int*   EI    = (const int*)d_in[2];
    const float* EA    = (const float*)d_in[3];
    const float* W1    = (const float*)d_in[4];
    const float* b1    = (const float*)d_in[5];
    const float* W2    = (const float*)d_in[6];
    const float* b2    = (const float*)d_in[7];
    const float* Wq    = (const float*)d_in[8];
    const float* bq    = (const float*)d_in[9];
    const float* Wk    = (const float*)d_in[10];
    const float* bk    = (const float*)d_in[11];
    const float* Wv    = (const float*)d_in[12];
    const float* bv    = (const float*)d_in[13];
    const float* We    = (const float*)d_in[14];
    const float* be    = (const float*)d_in[15];
    const float* Ws    = (const float*)d_in[16];
    const float* bs    = (const float*)d_in[17];
    const float* gamma = (const float*)d_in[18];
    const float* beta  = (const float*)d_in[19];
    float* out = (float*)d_out;

    float *pXS, *pXD, *pQ, *pK, *pV, *pEB, *pACC, *pH, *pNEA;
    float *pAMAX, *pDEN, *pGS, *pGQ;
    int *pGC;
    unsigned *pOUTU;
    cudaGetSymbolAddress((void**)&pXS,   g_XS);
    cudaGetSymbolAddress((void**)&pXD,   g_XD);
    cudaGetSymbolAddress((void**)&pQ,    g_Q);
    cudaGetSymbolAddress((void**)&pK,    g_K);
    cudaGetSymbolAddress((void**)&pV,    g_V);
    cudaGetSymbolAddress((void**)&pEB,   g_EB);
    cudaGetSymbolAddress((void**)&pACC,  g_ACC);
    cudaGetSymbolAddress((void**)&pH,    g_H);
    cudaGetSymbolAddress((void**)&pNEA,  g_NEA);
    cudaGetSymbolAddress((void**)&pAMAX, g_AMAX);
    cudaGetSymbolAddress((void**)&pDEN,  g_DEN);
    cudaGetSymbolAddress((void**)&pGS,   g_GS);
    cudaGetSymbolAddress((void**)&pGQ,   g_GQ);
    cudaGetSymbolAddress((void**)&pGC,   g_GC);
    cudaGetSymbolAddress((void**)&pOUTU, g_OUTU);

    const int MT_N = (NN + 127) / 128;   // 391
    const int MT_E = (EE + 127) / 128;   // 1172

    // graph node counts
    cudaMemsetAsync(pGC, 0, GG * sizeof(int));
    count_nodes<<<(NN + 255) / 256, 256>>>(batch);

    // edge MLP node-projections: Xs = x @ W1[0:320], Xd = x @ W1[320:640]
    sgemm<false><<<dim3(1, MT_N), 256>>>(x, W1,                       nullptr, pXS, NN, DD, EHH, EHH);
    sgemm<false><<<dim3(1, MT_N), 256>>>(x, W1 + (size_t)DD * EHH,    nullptr, pXD, NN, DD, EHH, EHH);

    // per-edge MLP for all 9 types
    {
        long totW = (long)NTT * EE;
        edge_mlp<<<(unsigned)((totW + 7) / 8), 256>>>(EI, EA, W1, b1, W2, b2);
    }

    // H = x
    cudaMemcpyAsync(pH, x, (size_t)NN * DD * sizeof(float), cudaMemcpyDeviceToDevice);

    for (int b = 0; b < NBB; b++) {
        cudaMemsetAsync(pACC, 0, (size_t)NN * DD * sizeof(float));
        for (int t = 0; t < NTT; t++) {
            size_t wi = (size_t)(b * NTT + t);
            const float* wq = Wq + wi * DD * DD;
            const float* wk = Wk + wi * DD * DD;
            const float* wv = Wv + wi * DD * DD;
            const float* ws = Ws + wi * DD * DD;
            const float* we = We + wi * EHH * DD;

            sgemm<false><<<dim3(5, MT_N), 256>>>(pH, wq, bq + wi * DD, pQ,   NN, DD, DD, DD);
            sgemm<false><<<dim3(5, MT_N), 256>>>(pH, wk, bk + wi * DD, pK,   NN, DD, DD, DD);
            sgemm<false><<<dim3(5, MT_N), 256>>>(pH, wv, bv + wi * DD, pV,   NN, DD, DD, DD);
            sgemm<true ><<<dim3(5, MT_N), 256>>>(pH, ws, bs + wi * DD, pACC, NN, DD, DD, DD);
            sgemm<false><<<dim3(5, MT_E), 256>>>(pNEA + (size_t)t * EE * EHH, we,
                                                 be + wi * DD, pEB, EE, EHH, DD, DD);

            fillf<<<(NN + 255) / 256, 256>>>(pAMAX, -INFINITY, NN);
            cudaMemsetAsync(pDEN, 0, NN * sizeof(float));

            const int* srcI = EI + ((size_t)t * 2) * EE;
            const int* dstI = srcI + EE;
            att_pass1<<<(EE + 7) / 8, 256>>>(srcI, dstI);
            att_pass2<<<(EE + 255) / 256, 256>>>(dstI);
            att_pass3<<<(EE + 7) / 8, 256>>>(srcI, dstI);
        }
        cudaMemsetAsync(pGS, 0, GG * sizeof(float));
        cudaMemsetAsync(pGQ, 0, GG * sizeof(float));
        gstats<<<(NN + 7) / 8, 256>>>(batch);
        gfinal<<<1, 256>>>();
        hupdate<<<(unsigned)(((size_t)NN * DD + 255) / 256), 256>>>(batch,
                                                                    gamma + (size_t)b * DD,
                                                                    beta  + (size_t)b * DD);
    }

    cudaMemsetAsync(pOUTU, 0, (size_t)GG * DD * sizeof(unsigned));
    maxred<<<(unsigned)(((size_t)NN * DD + 255) / 256), 256>>>(batch);
    finalize<<<(GG * DD + 255) / 256, 256>>>(out);
}

// round 4
// speedup vs baseline: 1.4505x; 1.4505x over previous
#include <cuda_runtime.h>
#include <math.h>

#define NN   50000
#define EE   150000
#define GG   200
#define DD   320
#define EDIN 15
#define EHH  32
#define NBB  3
#define NTT  9

// ---------------- scratch (static device globals; allocation-free) ----------------
__device__ float g_NEA[NTT * EE * EHH];   // per-type edge MLP output [9,150000,32]
__device__ float g_XS[NN * EHH];          // x @ W1[0:320]
__device__ float g_XD[NN * EHH];          // x @ W1[320:640]
__device__ float g_Q[NN * DD];
__device__ float g_K[NN * DD];
__device__ float g_V[NN * DD];
__device__ float g_EB[EE * DD];           // edge projection e = nea @ We + be
__device__ float g_ACC[NN * DD];
__device__ float g_H[NN * DD];
__device__ float g_AL[EE];                // alpha, reused as exp(alpha - amax)
__device__ float g_AMAX[NN];
__device__ float g_DEN[NN];
__device__ float g_GS[GG];
__device__ float g_GQ[GG];
__device__ int   g_GC[GG];
__device__ float g_MEAN[GG];
__device__ float g_RSTD[GG];
__device__ unsigned g_OUTU[GG * DD];

// ---------------- tf32 helpers ----------------
__device__ __forceinline__ unsigned f2tf32(float f)
{
    unsigned u;
    asm("cvt.rna.tf32.f32 %0, %1;" : "=r"(u) : "f"(f));
    return u;
}

__device__ __forceinline__ void mma_tf32(float* d, const unsigned* a, unsigned b0, unsigned b1)
{
    asm volatile(
        "mma.sync.aligned.m16n8k8.row.col.f32.tf32.tf32.f32 "
        "{%0,%1,%2,%3}, {%4,%5,%6,%7}, {%8,%9}, {%0,%1,%2,%3};"
        : "+f"(d[0]), "+f"(d[1]), "+f"(d[2]), "+f"(d[3])
        : "r"(a[0]), "r"(a[1]), "r"(a[2]), "r"(a[3]), "r"(b0), "r"(b1));
}

// ---------------- TF32 tensor-core GEMM: C[MxNout] = A[MxK] @ B[KxNout](ldb) (+bias)(+=C) ----
// BM=128, BN=64, BK=16, 256 threads, 8 warps arranged 4(m) x 2(n), warp tile 32x32.
// Requires K % 16 == 0 and Nout % 4 == 0 (call sites: K in {320,32}, Nout=320).
template<bool ACCUM>
__global__ void __launch_bounds__(256) mma_gemm(
    const float* __restrict__ A, const float* __restrict__ B,
    const float* __restrict__ bias, float* __restrict__ C,
    int M, int K, int Nout, int ldb)
{
    __shared__ unsigned As[128 * 20];   // As[m*20 + k], stride 20 -> conflict-free frags
    __shared__ unsigned Bs[16 * 72];    // Bs[k*72 + n], stride 72 -> conflict-free frags

    const int tid  = threadIdx.x;
    const int lane = tid & 31;
    const int wid  = tid >> 5;
    const int wm   = (wid & 3) * 32;    // warp m offset within 128
    const int wn   = (wid >> 2) * 32;   // warp n offset within 64
    const int m0 = blockIdx.y * 128;
    const int n0 = blockIdx.x * 64;

    const int ar = tid >> 1;            // A load: row 0..127
    const int ac = (tid & 1) * 8;       // A load: k col 0 or 8
    const int kr = tid >> 4;            // B load: k row 0..15
    const int nc = (tid & 15) * 4;      // B load: n col 0..60

    float acc[2][4][4];
#pragma unroll
    for (int mt = 0; mt < 2; mt++)
#pragma unroll
        for (int nt = 0; nt < 4; nt++)
#pragma unroll
            for (int i = 0; i < 4; i++) acc[mt][nt][i] = 0.f;

    const bool arow_ok = (m0 + ar) < M;
    const size_t abase = (size_t)(m0 + ar) * K;
    const bool bcol_ok = (n0 + nc) < Nout;

    for (int k0 = 0; k0 < K; k0 += 16) {
        // ---- stage A tile (128x16) ----
        float4 av0 = make_float4(0.f, 0.f, 0.f, 0.f);
        float4 av1 = av0;
        if (arow_ok) {
            av0 = *(const float4*)(A + abase + k0 + ac);
            av1 = *(const float4*)(A + abase + k0 + ac + 4);
        }
        unsigned* asp = &As[ar * 20 + ac];
        asp[0] = f2tf32(av0.x); asp[1] = f2tf32(av0.y);
        asp[2] = f2tf32(av0.z); asp[3] = f2tf32(av0.w);
        asp[4] = f2tf32(av1.x); asp[5] = f2tf32(av1.y);
        asp[6] = f2tf32(av1.z); asp[7] = f2tf32(av1.w);
        // ---- stage B tile (16x64) ----
        float4 bv = make_float4(0.f, 0.f, 0.f, 0.f);
        if (bcol_ok)
            bv = *(const float4*)(B + (size_t)(k0 + kr) * ldb + n0 + nc);
        unsigned* bsp = &Bs[kr * 72 + nc];
        bsp[0] = f2tf32(bv.x); bsp[1] = f2tf32(bv.y);
        bsp[2] = f2tf32(bv.z); bsp[3] = f2tf32(bv.w);
        __syncthreads();

#pragma unroll
        for (int ks = 0; ks < 16; ks += 8) {
            unsigned af[2][4];
#pragma unroll
            for (int mt = 0; mt < 2; mt++) {
                int r = wm + mt * 16 + (lane >> 2);
                int c = ks + (lane & 3);
                af[mt][0] = As[r * 20 + c];
                af[mt][1] = As[(r + 8) * 20 + c];
                af[mt][2] = As[r * 20 + c + 4];
                af[mt][3] = As[(r + 8) * 20 + c + 4];
            }
#pragma unroll
            for (int nt = 0; nt < 4; nt++) {
                int bn = wn + nt * 8 + (lane >> 2);
                unsigned b0 = Bs[(ks + (lane & 3)) * 72 + bn];
                unsigned b1 = Bs[(ks + 4 + (lane & 3)) * 72 + bn];
#pragma unroll
                for (int mt = 0; mt < 2; mt++)
                    mma_tf32(acc[mt][nt], af[mt], b0, b1);
            }
        }
        __syncthreads();
    }

    // ---- epilogue ----
#pragma unroll
    for (int mt = 0; mt < 2; mt++) {
        int r0 = m0 + wm + mt * 16 + (lane >> 2);
#pragma unroll
        for (int nt = 0; nt < 4; nt++) {
            int c = n0 + wn + nt * 8 + 2 * (lane & 3);
            if (c >= Nout) continue;
            float bx = bias ? bias[c] : 0.f;
            float by = bias ? bias[c + 1] : 0.f;
#pragma unroll
            for (int half = 0; half < 2; half++) {
                int row = r0 + half * 8;
                if (row >= M) continue;
                float vx = acc[mt][nt][half * 2 + 0] + bx;
                float vy = acc[mt][nt][half * 2 + 1] + by;
                float* cp = C + (size_t)row * Nout + c;
                if (ACCUM) { vx += cp[0]; vy += cp[1]; }
                cp[0] = vx; cp[1] = vy;
            }
        }
    }
}

// ---------------- small SGEMM (used only for XS/XD, Nout=32) ----------------
template<bool ACCUM>
__global__ void __launch_bounds__(256) sgemm(
    const float* __restrict__ A, const float* __restrict__ B,
    const float* __restrict__ bias, float* __restrict__ C,
    int M, int K, int Nout, int ldb)
{
    __shared__ __align__(16) float As[16][132];
    __shared__ __align__(16) float Bs[16][64];

    int tid = threadIdx.x;
    int tx = tid & 15, ty = tid >> 4;
    int m0 = blockIdx.y * 128, n0 = blockIdx.x * 64;

    float acc[8][4];
#pragma unroll
    for (int i = 0; i < 8; i++)
#pragma unroll
        for (int j = 0; j < 4; j++) acc[i][j] = 0.f;

    int ar = tid >> 2;
    int ac = (tid & 3) * 4;
    int bk = tid >> 4;
    int bc = (tid & 15) * 4;

    for (int k0 = 0; k0 < K; k0 += 16) {
#pragma unroll
        for (int rr = 0; rr < 2; rr++) {
            int row = m0 + ar + rr * 64;
            float4 av = make_float4(0.f, 0.f, 0.f, 0.f);
            if (row < M) av = *(const float4*)(A + (size_t)row * K + k0 + ac);
            As[ac + 0][ar + rr * 64] = av.x;
            As[ac + 1][ar + rr * 64] = av.y;
            As[ac + 2][ar + rr * 64] = av.z;
            As[ac + 3][ar + rr * 64] = av.w;
        }
        {
            float4 bv = make_float4(0.f, 0.f, 0.f, 0.f);
            if (n0 + bc < Nout)
                bv = *(const float4*)(B + (size_t)(k0 + bk) * ldb + n0 + bc);
            *(float4*)&Bs[bk][bc] = bv;
        }
        __syncthreads();
#pragma unroll
        for (int k = 0; k < 16; k++) {
            float a[8], b[4];
            *(float4*)(a)     = *(const float4*)&As[k][ty * 8];
            *(float4*)(a + 4) = *(const float4*)&As[k][ty * 8 + 4];
            *(float4*)(b)     = *(const float4*)&Bs[k][tx * 4];
#pragma unroll
            for (int i = 0; i < 8; i++)
#pragma unroll
                for (int j = 0; j < 4; j++)
                    acc[i][j] += a[i] * b[j];
        }
        __syncthreads();
    }

#pragma unroll
    for (int i = 0; i < 8; i++) {
        int row = m0 + ty * 8 + i;
        if (row >= M) continue;
#pragma unroll
        for (int j = 0; j < 4; j++) {
            int col = n0 + tx * 4 + j;
            if (col >= Nout) continue;
            float v = acc[i][j];
            if (bias) v += bias[col];
            if (ACCUM) v += C[(size_t)row * Nout + col];
            C[(size_t)row * Nout + col] = v;
        }
    }
}

// ---------------- edge MLP: nea = (leaky(Xs[src]+Xd[dst]+ea@W1e+b1)) @ W2 + b2 ----------
__global__ void edge_mlp(const int* __restrict__ EI, const float* __restrict__ EA,
                         const float* __restrict__ W1, const float* __restrict__ b1,
                         const float* __restrict__ W2, const float* __restrict__ b2)
{
    __shared__ float sW1e[EDIN * EHH];
    __shared__ float sW2[EHH * EHH];
    __shared__ float sb1[EHH], sb2[EHH];
    int tid = threadIdx.x;
    for (int i = tid; i < EDIN * EHH; i += blockDim.x) sW1e[i] = W1[640 * EHH + i];
    for (int i = tid; i < EHH * EHH; i += blockDim.x)  sW2[i]  = W2[i];
    if (tid < EHH) { sb1[tid] = b1[tid]; sb2[tid] = b2[tid]; }
    __syncthreads();

    long w = (long)blockIdx.x * (blockDim.x / 32) + tid / 32;
    int lane = tid & 31;
    if (w >= (long)NTT * EE) return;
    int t = (int)(w / EE);
    int e = (int)(w % EE);
    int src = EI[((size_t)t * 2 + 0) * EE + e];
    int dst = EI[((size_t)t * 2 + 1) * EE + e];

    float eav = 0.f;
    if (lane < EDIN) eav = EA[((size_t)t * EE + e) * EDIN + lane];

    float h = sb1[lane] + g_XS[(size_t)src * EHH + lane] + g_XD[(size_t)dst * EHH + lane];
#pragma unroll
    for (int i = 0; i < EDIN; i++)
        h += __shfl_sync(0xffffffffu, eav, i) * sW1e[i * EHH + lane];
    h = h > 0.f ? h : 0.01f * h;

    float o = sb2[lane];
#pragma unroll
    for (int i = 0; i < EHH; i++)
        o += __shfl_sync(0xffffffffu, h, i) * sW2[i * EHH + lane];

    g_NEA[((size_t)t * EE + e) * EHH + lane] = o;
}

// ---------------- attention passes ----------------
__global__ void att_pass1(const int* __restrict__ srcI, const int* __restrict__ dstI)
{
    int w = blockIdx.x * (blockDim.x / 32) + threadIdx.x / 32;
    int lane = threadIdx.x & 31;
    if (w >= EE) return;
    int src = srcI[w], dst = dstI[w];
    const float* q  = g_Q  + (size_t)dst * DD;
    const float* kk = g_K  + (size_t)src * DD;
    const float* eb = g_EB + (size_t)w * DD;
    float s = 0.f;
#pragma unroll
    for (int c = lane; c < DD; c += 32)
        s += q[c] * (kk[c] + eb[c]);
#pragma unroll
    for (int off = 16; off; off >>= 1) s += __shfl_xor_sync(0xffffffffu, s, off);
    if (lane == 0) {
        float al = s * 0.05590169943749474f;  // 1/sqrt(320)
        g_AL[w] = al;
        if (al >= 0.f) atomicMax((int*)&g_AMAX[dst], __float_as_int(al));
        else           atomicMin((unsigned*)&g_AMAX[dst], __float_as_uint(al));
    }
}

__global__ void att_pass2(const int* __restrict__ dstI)
{
    int e = blockIdx.x * blockDim.x + threadIdx.x;
    if (e >= EE) return;
    int dst = dstI[e];
    float ex = expf(g_AL[e] - g_AMAX[dst]);
    g_AL[e] = ex;
    atomicAdd(&g_DEN[dst], ex);
}

__global__ void att_pass3(const int* __restrict__ srcI, const int* __restrict__ dstI)
{
    int w = blockIdx.x * (blockDim.x / 32) + threadIdx.x / 32;
    int lane = threadIdx.x & 31;
    if (w >= EE) return;
    int src = srcI[w], dst = dstI[w];
    float wgt = g_AL[w] / (g_DEN[dst] + 1e-16f);
    const float* v  = g_V  + (size_t)src * DD;
    const float* eb = g_EB + (size_t)w * DD;
    float* out = g_ACC + (size_t)dst * DD;
#pragma unroll
    for (int c = lane; c < DD; c += 32)
        atomicAdd(&out[c], wgt * (v[c] + eb[c]));
}

// ---------------- misc ----------------
__global__ void fillf(float* p, float v, int n)
{
    int i = blockIdx.x * blockDim.x + threadIdx.x;
    if (i < n) p[i] = v;
}

__global__ void count_nodes(const int* __restrict__ batch)
{
    int i = blockIdx.x * blockDim.x + threadIdx.x;
    if (i < NN) atomicAdd(&g_GC[batch[i]], 1);
}

__global__ void gstats(const int* __restrict__ batch)
{
    int w = blockIdx.x * (blockDim.x / 32) + threadIdx.x / 32;
    int lane = threadIdx.x & 31;
    if (w >= NN) return;
    const float* a = g_ACC + (size_t)w * DD;
    float s1 = 0.f, s2 = 0.f;
#pragma unroll
    for (int c = lane; c < DD; c += 32) {
        float v = a[c] * (1.f / 9.f);
        v = v > 0.f ? v : 0.01f * v;
        s1 += v; s2 += v * v;
    }
#pragma unroll
    for (int off = 16; off; off >>= 1) {
        s1 += __shfl_xor_sync(0xffffffffu, s1, off);
        s2 += __shfl_xor_sync(0xffffffffu, s2, off);
    }
    if (lane == 0) {
        int g = batch[w];
        atomicAdd(&g_GS[g], s1);
        atomicAdd(&g_GQ[g], s2);
    }
}

__global__ void gfinal()
{
    int g = blockIdx.x * blockDim.x + threadIdx.x;
    if (g >= GG) return;
    float cnt  = (float)g_GC[g];
    float norm = fmaxf(cnt, 1.f) * (float)DD;
    float mean = g_GS[g] / norm;
    float var  = fmaxf(g_GQ[g] / norm - mean * mean, 0.f);
    g_MEAN[g] = mean;
    g_RSTD[g] = rsqrtf(var + 1e-5f);
}

__global__ void hupdate(const int* __restrict__ batch,
                        const float* __restrict__ gamma, const float* __restrict__ beta)
{
    size_t i = (size_t)blockIdx.x * blockDim.x + threadIdx.x;
    if (i >= (size_t)NN * DD) return;
    int node = (int)(i / DD), c = (int)(i % DD);
    int g = batch[node];
    float v = g_ACC[i] * (1.f / 9.f);
    v = v > 0.f ? v : 0.01f * v;
    float xn = (v - g_MEAN[g]) * g_RSTD[g] * gamma[c] + beta[c];
    g_H[i] = 0.5f * (g_H[i] + xn);
}

__device__ __forceinline__ unsigned fkey(float f)
{
    unsigned u = __float_as_uint(f);
    return (u & 0x80000000u) ? ~u : (u | 0x80000000u);
}
__device__ __forceinline__ float funkey(unsigned u)
{
    return (u & 0x80000000u) ? __uint_as_float(u & 0x7FFFFFFFu) : __uint_as_float(~u);
}

__global__ void maxred(const int* __restrict__ batch)
{
    size_t i = (size_t)blockIdx.x * blockDim.x + threadIdx.x;
    if (i >= (size_t)NN * DD) return;
    int node = (int)(i / DD), c = (int)(i % DD);
    atomicMax(&g_OUTU[(size_t)batch[node] * DD + c], fkey(g_H[i]));
}

__global__ void finalize(float* __restrict__ out)
{
    int i = blockIdx.x * blockDim.x + threadIdx.x;
    if (i < GG * DD) out[i] = funkey(g_OUTU[i]);
}

// ---------------- host orchestration ----------------
extern "C" void kernel_launch(void* const* d_in, const int* in_sizes, int n_in,
                              void* d_out, int out_size)
{
    const float* x     = (const float*)d_in[0];
    const int*   batch = (const int*)d_in[1];
    const int*   EI    = (const int*)d_in[2];
    const float* EA    = (const float*)d_in[3];
    const float* W1    = (const float*)d_in[4];
    const float* b1    = (const float*)d_in[5];
    const float* W2    = (const float*)d_in[6];
    const float* b2    = (const float*)d_in[7];
    const float* Wq    = (const float*)d_in[8];
    const float* bq    = (const float*)d_in[9];
    const float* Wk    = (const float*)d_in[10];
    const float* bk    = (const float*)d_in[11];
    const float* Wv    = (const float*)d_in[12];
    const float* bv    = (const float*)d_in[13];
    const float* We    = (const float*)d_in[14];
    const float* be    = (const float*)d_in[15];
    const float* Ws    = (const float*)d_in[16];
    const float* bs    = (const float*)d_in[17];
    const float* gamma = (const float*)d_in[18];
    const float* beta  = (const float*)d_in[19];
    float* out = (float*)d_out;

    float *pXS, *pXD, *pQ, *pK, *pV, *pEB, *pACC, *pH, *pNEA;
    float *pAMAX, *pDEN, *pGS, *pGQ;
    int *pGC;
    unsigned *pOUTU;
    cudaGetSymbolAddress((void**)&pXS,   g_XS);
    cudaGetSymbolAddress((void**)&pXD,   g_XD);
    cudaGetSymbolAddress((void**)&pQ,    g_Q);
    cudaGetSymbolAddress((void**)&pK,    g_K);
    cudaGetSymbolAddress((void**)&pV,    g_V);
    cudaGetSymbolAddress((void**)&pEB,   g_EB);
    cudaGetSymbolAddress((void**)&pACC,  g_ACC);
    cudaGetSymbolAddress((void**)&pH,    g_H);
    cudaGetSymbolAddress((void**)&pNEA,  g_NEA);
    cudaGetSymbolAddress((void**)&pAMAX, g_AMAX);
    cudaGetSymbolAddress((void**)&pDEN,  g_DEN);
    cudaGetSymbolAddress((void**)&pGS,   g_GS);
    cudaGetSymbolAddress((void**)&pGQ,   g_GQ);
    cudaGetSymbolAddress((void**)&pGC,   g_GC);
    cudaGetSymbolAddress((void**)&pOUTU, g_OUTU);

    const int MT_N128 = (NN + 127) / 128;   // 391
    const int MT_E128 = (EE + 127) / 128;   // 1172

    // graph node counts
    cudaMemsetAsync(pGC, 0, GG * sizeof(int));
    count_nodes<<<(NN + 255) / 256, 256>>>(batch);

    // edge MLP node-projections: Xs = x @ W1[0:320], Xd = x @ W1[320:640]
    sgemm<false><<<dim3(1, MT_N128), 256>>>(x, W1,                    nullptr, pXS, NN, DD, EHH, EHH);
    sgemm<false><<<dim3(1, MT_N128), 256>>>(x, W1 + (size_t)DD * EHH, nullptr, pXD, NN, DD, EHH, EHH);

    // per-edge MLP for all 9 types
    {
        long totW = (long)NTT * EE;
        edge_mlp<<<(unsigned)((totW + 7) / 8), 256>>>(EI, EA, W1, b1, W2, b2);
    }

    // H = x
    cudaMemcpyAsync(pH, x, (size_t)NN * DD * sizeof(float), cudaMemcpyDeviceToDevice);

    for (int b = 0; b < NBB; b++) {
        cudaMemsetAsync(pACC, 0, (size_t)NN * DD * sizeof(float));
        for (int t = 0; t < NTT; t++) {
            size_t wi = (size_t)(b * NTT + t);
            const float* wq = Wq + wi * DD * DD;
            const float* wk = Wk + wi * DD * DD;
            const float* wv = Wv + wi * DD * DD;
            const float* ws = Ws + wi * DD * DD;
            const float* we = We + wi * EHH * DD;

            mma_gemm<false><<<dim3(5, MT_N128), 256>>>(pH, wq, bq + wi * DD, pQ,   NN, DD, DD, DD);
            mma_gemm<false><<<dim3(5, MT_N128), 256>>>(pH, wk, bk + wi * DD, pK,   NN, DD, DD, DD);
            mma_gemm<false><<<dim3(5, MT_N128), 256>>>(pH, wv, bv + wi * DD, pV,   NN, DD, DD, DD);
            mma_gemm<true ><<<dim3(5, MT_N128), 256>>>(pH, ws, bs + wi * DD, pACC, NN, DD, DD, DD);
            mma_gemm<false><<<dim3(5, MT_E128), 256>>>(pNEA + (size_t)t * EE * EHH, we,
                                                       be + wi * DD, pEB, EE, EHH, DD, DD);

            fillf<<<(NN + 255) / 256, 256>>>(pAMAX, -INFINITY, NN);
            cudaMemsetAsync(pDEN, 0, NN * sizeof(float));

            const int* srcI = EI + ((size_t)t * 2) * EE;
            const int* dstI = srcI + EE;
            att_pass1<<<(EE + 7) / 8, 256>>>(srcI, dstI);
            att_pass2<<<(EE + 255) / 256, 256>>>(dstI);
            att_pass3<<<(EE + 7) / 8, 256>>>(srcI, dstI);
        }
        cudaMemsetAsync(pGS, 0, GG * sizeof(float));
        cudaMemsetAsync(pGQ, 0, GG * sizeof(float));
        gstats<<<(NN + 7) / 8, 256>>>(batch);
        gfinal<<<1, 256>>>();
        hupdate<<<(unsigned)(((size_t)NN * DD + 255) / 256), 256>>>(batch,
                                                                    gamma + (size_t)b * DD,
                                                                    beta  + (size_t)b * DD);
    }

    cudaMemsetAsync(pOUTU, 0, (size_t)GG * DD * sizeof(unsigned));
    maxred<<<(unsigned)(((size_t)NN * DD + 255) / 256), 256>>>(batch);
    finalize<<<(GG * DD + 255) / 256, 256>>>(out);
}

// round 5
// speedup vs baseline: 2.5662x; 1.7692x over previous
#include <cuda_runtime.h>
#include <math.h>

#define NN   50000
#define EE   150000
#define GG   200
#define DD   320
#define EDIN 15
#define EHH  32
#define NBB  3
#define NTT  9
#define NE9  (NTT * EE)

// ---------------- scratch (static device globals; allocation-free) ----------------
__device__ float g_NEA[NTT * EE * EHH];    // per-type edge MLP output [9,150000,32]
__device__ float g_XS[NN * EHH];
__device__ float g_XD[NN * EHH];
__device__ float g_Q[NTT * NN * DD];       // per-type Q for current block
__device__ float g_K[NTT * NN * DD];
__device__ float g_V[NTT * NN * DD];
__device__ float g_QW[NTT * NN * EHH];     // Q @ We^T  [9,N,32]
__device__ float g_WNEA[NN * NTT * EHH];   // node-major [N, 9*32]
__device__ float g_ACC[NN * DD];
__device__ float g_H[NN * DD];
__device__ float g_AL[NE9];                // alpha, then exp(alpha - amax)
__device__ float g_AMAX[NTT * NN];
__device__ float g_DEN[NTT * NN];
__device__ float g_WSUM[NBB * DD * DD];    // sum_t Ws[b,t]
__device__ float g_BSUM[NBB * DD];
__device__ float g_WET[NBB * NTT * DD * EHH];  // We^T per (b,t): [320][32]
__device__ int   g_CNT[NN + 1];            // CSR offsets (dst-sorted, all 9 types)
__device__ int   g_POS[NN];
__device__ int   g_CSRE[NE9];              // edge index w = t*EE+e
__device__ int   g_CSRS[NE9];              // src node
__device__ float g_GS[GG];
__device__ float g_GQ[GG];
__device__ int   g_GC[GG];
__device__ float g_MEAN[GG];
__device__ float g_RSTD[GG];
__device__ unsigned g_OUTU[GG * DD];

// ---------------- tf32 / cp.async helpers ----------------
__device__ __forceinline__ unsigned f2tf32(float f)
{
    unsigned u;
    asm("cvt.rna.tf32.f32 %0, %1;" : "=r"(u) : "f"(f));
    return u;
}

__device__ __forceinline__ void mma_tf32(float* d, const unsigned* a, unsigned b0, unsigned b1)
{
    asm volatile(
        "mma.sync.aligned.m16n8k8.row.col.f32.tf32.tf32.f32 "
        "{%0,%1,%2,%3}, {%4,%5,%6,%7}, {%8,%9}, {%0,%1,%2,%3};"
        : "+f"(d[0]), "+f"(d[1]), "+f"(d[2]), "+f"(d[3])
        : "r"(a[0]), "r"(a[1]), "r"(a[2]), "r"(a[3]), "r"(b0), "r"(b1));
}

__device__ __forceinline__ void cp16(unsigned dst, const float* src, bool p)
{
    asm volatile("cp.async.cg.shared.global [%0], [%1], 16, %2;"
                 :: "r"(dst), "l"(src), "r"(p ? 16 : 0));
}
__device__ __forceinline__ void cp_commit() { asm volatile("cp.async.commit_group;"); }
template<int N> __device__ __forceinline__ void cp_wait() { asm volatile("cp.async.wait_group %0;" :: "n"(N)); }

// ---------------- TF32 tensor-core GEMM, cp.async double-buffered ----------------
// C[MxNout] = A[MxK] @ B[KxNout](ldb) (+bias)(+=C); z-batched via element strides.
// BM=128, BN=64, BK=16, 256 threads, 8 warps 4(m)x2(n), warp tile 32x32.
// Requires K%16==0, Nout%64==0 at mma call sites (Nout=320 always here).
template<bool ACCUM>
__global__ void __launch_bounds__(256) mma_gemm(
    const float* __restrict__ A, const float* __restrict__ B,
    const float* __restrict__ bias, float* __restrict__ C,
    int M, int K, int Nout, int ldb,
    long aZ, long bZ, long cZ, long biasZ)
{
    __shared__ float As[2][128 * 20];
    __shared__ float Bs[2][16 * 72];

    const int z = blockIdx.z;
    A += (size_t)z * aZ; B += (size_t)z * bZ; C += (size_t)z * cZ;
    if (bias) bias += (size_t)z * biasZ;

    const int tid  = threadIdx.x;
    const int lane = tid & 31;
    const int wid  = tid >> 5;
    const int wm   = (wid & 3) * 32;
    const int wn   = (wid >> 2) * 32;
    const int m0 = blockIdx.y * 128;
    const int n0 = blockIdx.x * 64;

    const int ar = tid >> 1;
    const int ac = (tid & 1) * 8;
    const int kr = tid >> 4;
    const int nc = (tid & 15) * 4;

    const bool arow_ok = (m0 + ar) < M;
    const float* aptr = A + (size_t)(m0 + ar) * K + ac;
    const float* bptr = B + (size_t)kr * ldb + n0 + nc;

    unsigned sa0 = (unsigned)__cvta_generic_to_shared(&As[0][ar * 20 + ac]);
    unsigned sa1 = (unsigned)__cvta_generic_to_shared(&As[1][ar * 20 + ac]);
    unsigned sb0 = (unsigned)__cvta_generic_to_shared(&Bs[0][kr * 72 + nc]);
    unsigned sb1 = (unsigned)__cvta_generic_to_shared(&Bs[1][kr * 72 + nc]);

    float acc[2][4][4];
#pragma unroll
    for (int mt = 0; mt < 2; mt++)
#pragma unroll
        for (int nt = 0; nt < 4; nt++)
#pragma unroll
            for (int i = 0; i < 4; i++) acc[mt][nt][i] = 0.f;

    const int nk = K / 16;

    // prologue: stage 0
    cp16(sa0, aptr, arow_ok);
    cp16(sa0 + 16, aptr + 4, arow_ok);
    cp16(sb0, bptr, true);
    cp_commit();

    for (int kt = 0; kt < nk; kt++) {
        if (kt + 1 < nk) {
            int k0 = (kt + 1) * 16;
            unsigned da = (kt & 1) ? sa0 : sa1;
            unsigned db = (kt & 1) ? sb0 : sb1;
            cp16(da, aptr + k0, arow_ok);
            cp16(da + 16, aptr + k0 + 4, arow_ok);
            cp16(db, bptr + (size_t)k0 * ldb, true);
            cp_commit();
            cp_wait<1>();
        } else {
            cp_wait<0>();
        }
        __syncthreads();

        const float* Ab = As[kt & 1];
        const float* Bb = Bs[kt & 1];
#pragma unroll
        for (int ks = 0; ks < 16; ks += 8) {
            unsigned af[2][4];
#pragma unroll
            for (int mt = 0; mt < 2; mt++) {
                int r = wm + mt * 16 + (lane >> 2);
                int c = ks + (lane & 3);
                af[mt][0] = f2tf32(Ab[r * 20 + c]);
                af[mt][1] = f2tf32(Ab[(r + 8) * 20 + c]);
                af[mt][2] = f2tf32(Ab[r * 20 + c + 4]);
                af[mt][3] = f2tf32(Ab[(r + 8) * 20 + c + 4]);
            }
#pragma unroll
            for (int nt = 0; nt < 4; nt++) {
                int bn = wn + nt * 8 + (lane >> 2);
                unsigned b0 = f2tf32(Bb[(ks + (lane & 3)) * 72 + bn]);
                unsigned b1 = f2tf32(Bb[(ks + 4 + (lane & 3)) * 72 + bn]);
#pragma unroll
                for (int mt = 0; mt < 2; mt++)
                    mma_tf32(acc[mt][nt], af[mt], b0, b1);
            }
        }
        __syncthreads();
    }

#pragma unroll
    for (int mt = 0; mt < 2; mt++) {
        int r0 = m0 + wm + mt * 16 + (lane >> 2);
#pragma unroll
        for (int nt = 0; nt < 4; nt++) {
            int c = n0 + wn + nt * 8 + 2 * (lane & 3);
            float bx = bias ? bias[c] : 0.f;
            float by = bias ? bias[c + 1] : 0.f;
#pragma unroll
            for (int half = 0; half < 2; half++) {
                int row = r0 + half * 8;
                if (row >= M) continue;
                float vx = acc[mt][nt][half * 2 + 0] + bx;
                float vy = acc[mt][nt][half * 2 + 1] + by;
                float* cp = C + (size_t)row * Nout + c;
                if (ACCUM) { vx += cp[0]; vy += cp[1]; }
                cp[0] = vx; cp[1] = vy;
            }
        }
    }
}

// ---------------- small SGEMM (Nout=32 paths: XS/XD, QW), z-batched ----------------
__global__ void __launch_bounds__(256) sgemm(
    const float* __restrict__ A, const float* __restrict__ B,
    const float* __restrict__ bias, float* __restrict__ C,
    int M, int K, int Nout, int ldb,
    long aZ, long bZ, long cZ)
{
    __shared__ __align__(16) float As[16][132];
    __shared__ __align__(16) float Bs[16][64];

    const int z = blockIdx.z;
    A += (size_t)z * aZ; B += (size_t)z * bZ; C += (size_t)z * cZ;

    int tid = threadIdx.x;
    int tx = tid & 15, ty = tid >> 4;
    int m0 = blockIdx.y * 128, n0 = blockIdx.x * 64;

    float acc[8][4];
#pragma unroll
    for (int i = 0; i < 8; i++)
#pragma unroll
        for (int j = 0; j < 4; j++) acc[i][j] = 0.f;

    int ar = tid >> 2;
    int ac = (tid & 3) * 4;
    int bk = tid >> 4;
    int bc = (tid & 15) * 4;

    for (int k0 = 0; k0 < K; k0 += 16) {
#pragma unroll
        for (int rr = 0; rr < 2; rr++) {
            int row = m0 + ar + rr * 64;
            float4 av = make_float4(0.f, 0.f, 0.f, 0.f);
            if (row < M) av = *(const float4*)(A + (size_t)row * K + k0 + ac);
            As[ac + 0][ar + rr * 64] = av.x;
            As[ac + 1][ar + rr * 64] = av.y;
            As[ac + 2][ar + rr * 64] = av.z;
            As[ac + 3][ar + rr * 64] = av.w;
        }
        {
            float4 bv = make_float4(0.f, 0.f, 0.f, 0.f);
            if (n0 + bc < Nout)
                bv = *(const float4*)(B + (size_t)(k0 + bk) * ldb + n0 + bc);
            *(float4*)&Bs[bk][bc] = bv;
        }
        __syncthreads();
#pragma unroll
        for (int k = 0; k < 16; k++) {
            float a[8], b[4];
            *(float4*)(a)     = *(const float4*)&As[k][ty * 8];
            *(float4*)(a + 4) = *(const float4*)&As[k][ty * 8 + 4];
            *(float4*)(b)     = *(const float4*)&Bs[k][tx * 4];
#pragma unroll
            for (int i = 0; i < 8; i++)
#pragma unroll
                for (int j = 0; j < 4; j++)
                    acc[i][j] += a[i] * b[j];
        }
        __syncthreads();
    }

#pragma unroll
    for (int i = 0; i < 8; i++) {
        int row = m0 + ty * 8 + i;
        if (row >= M) continue;
#pragma unroll
        for (int j = 0; j < 4; j++) {
            int col = n0 + tx * 4 + j;
            if (col >= Nout) continue;
            float v = acc[i][j];
            if (bias) v += bias[col];
            C[(size_t)row * Nout + col] = v;
        }
    }
}

// ---------------- weight preprocessing ----------------
__global__ void wsum_all(const float* __restrict__ Ws, const float* __restrict__ bs)
{
    int i = blockIdx.x * blockDim.x + threadIdx.x;
    if (i < NBB * DD * DD) {
        int b = i / (DD * DD), r = i % (DD * DD);
        float s = 0.f;
#pragma unroll
        for (int t = 0; t < NTT; t++) s += Ws[((size_t)b * NTT + t) * DD * DD + r];
        g_WSUM[i] = s;
    } else {
        int j = i - NBB * DD * DD;
        if (j < NBB * DD) {
            int b = j / DD, c = j % DD;
            float s = 0.f;
#pragma unroll
            for (int t = 0; t < NTT; t++) s += bs[((size_t)b * NTT + t) * DD + c];
            g_BSUM[j] = s;
        }
    }
}

__global__ void wet_all(const float* __restrict__ We)
{
    int i = blockIdx.x * blockDim.x + threadIdx.x;
    if (i >= NBB * NTT * DD * EHH) return;
    int n = i & 31;
    int k = (i >> 5) % DD;
    int bt = i / (DD * EHH);
    g_WET[i] = We[((size_t)bt * EHH + n) * DD + k];
}

// ---------------- CSR build (dst-sorted over all 9 types) ----------------
__global__ void csr_count(const int* __restrict__ EI)
{
    int i = blockIdx.x * blockDim.x + threadIdx.x;
    if (i >= NE9) return;
    int t = i / EE, e = i - t * EE;
    int dst = EI[((size_t)t * 2 + 1) * EE + e];
    atomicAdd(&g_CNT[dst], 1);
}

__global__ void __launch_bounds__(1024) csr_scan()
{
    __shared__ int sm[1024];
    int tid = threadIdx.x;
    const int CH = (NN + 1023) / 1024;
    int lo = tid * CH, hi = lo + CH < NN ? lo + CH : NN;
    int s = 0;
    for (int i = lo; i < hi; i++) s += g_CNT[i];
    sm[tid] = s;
    __syncthreads();
    for (int off = 1; off < 1024; off <<= 1) {
        int v = (tid >= off) ? sm[tid - off] : 0;
        __syncthreads();
        sm[tid] += v;
        __syncthreads();
    }
    int run = (tid > 0) ? sm[tid - 1] : 0;
    for (int i = lo; i < hi; i++) {
        int c = g_CNT[i];
        g_CNT[i] = run;
        g_POS[i] = run;
        run += c;
    }
    if (tid == 1023) g_CNT[NN] = sm[1023];
}

__global__ void csr_fill(const int* __restrict__ EI)
{
    int i = blockIdx.x * blockDim.x + threadIdx.x;
    if (i >= NE9) return;
    int t = i / EE, e = i - t * EE;
    int dst = EI[((size_t)t * 2 + 1) * EE + e];
    int src = EI[((size_t)t * 2 + 0) * EE + e];
    int p = atomicAdd(&g_POS[dst], 1);
    g_CSRE[p] = i;
    g_CSRS[p] = src;
}

// ---------------- edge MLP ----------------
__global__ void edge_mlp(const int* __restrict__ EI, const float* __restrict__ EA,
                         const float* __restrict__ W1, const float* __restrict__ b1,
                         const float* __restrict__ W2, const float* __restrict__ b2)
{
    __shared__ float sW1e[EDIN * EHH];
    __shared__ float sW2[EHH * EHH];
    __shared__ float sb1[EHH], sb2[EHH];
    int tid = threadIdx.x;
    for (int i = tid; i < EDIN * EHH; i += blockDim.x) sW1e[i] = W1[640 * EHH + i];
    for (int i = tid; i < EHH * EHH; i += blockDim.x)  sW2[i]  = W2[i];
    if (tid < EHH) { sb1[tid] = b1[tid]; sb2[tid] = b2[tid]; }
    __syncthreads();

    long w = (long)blockIdx.x * (blockDim.x / 32) + tid / 32;
    int lane = tid & 31;
    if (w >= (long)NE9) return;
    int t = (int)(w / EE);
    int e = (int)(w % EE);
    int src = EI[((size_t)t * 2 + 0) * EE + e];
    int dst = EI[((size_t)t * 2 + 1) * EE + e];

    float eav = 0.f;
    if (lane < EDIN) eav = EA[((size_t)t * EE + e) * EDIN + lane];

    float h = sb1[lane] + g_XS[(size_t)src * EHH + lane] + g_XD[(size_t)dst * EHH + lane];
#pragma unroll
    for (int i = 0; i < EDIN; i++)
        h += __shfl_sync(0xffffffffu, eav, i) * sW1e[i * EHH + lane];
    h = h > 0.f ? h : 0.01f * h;

    float o = sb2[lane];
#pragma unroll
    for (int i = 0; i < EHH; i++)
        o += __shfl_sync(0xffffffffu, h, i) * sW2[i * EHH + lane];

    g_NEA[((size_t)t * EE + e) * EHH + lane] = o;
}

// ---------------- attention ----------------
__global__ void fill_amax_den()
{
    int i = blockIdx.x * blockDim.x + threadIdx.x;
    if (i < NTT * NN) { g_AMAX[i] = -INFINITY; g_DEN[i] = 0.f; }
}

__global__ void att_pass1(const int* __restrict__ EI)
{
    long w = (long)blockIdx.x * 8 + (threadIdx.x >> 5);
    int lane = threadIdx.x & 31;
    if (w >= NE9) return;
    int t = (int)(w / EE), e = (int)(w - (long)t * EE);
    int src = EI[((size_t)t * 2 + 0) * EE + e];
    int dst = EI[((size_t)t * 2 + 1) * EE + e];
    const float* q = g_Q + ((size_t)t * NN + dst) * DD;
    const float* k = g_K + ((size_t)t * NN + src) * DD;
    float s = g_QW[((size_t)t * NN + dst) * EHH + lane] * g_NEA[((size_t)t * EE + e) * EHH + lane];
#pragma unroll
    for (int i = 0; i < 10; i++)
        s += q[lane + 32 * i] * k[lane + 32 * i];
#pragma unroll
    for (int off = 16; off; off >>= 1) s += __shfl_xor_sync(0xffffffffu, s, off);
    if (lane == 0) {
        float al = s * 0.05590169943749474f;
        g_AL[w] = al;
        float* am = &g_AMAX[(size_t)t * NN + dst];
        if (al >= 0.f) atomicMax((int*)am, __float_as_int(al));
        else           atomicMin((unsigned*)am, __float_as_uint(al));
    }
}

__global__ void att_pass2(const int* __restrict__ EI)
{
    long i = (long)blockIdx.x * blockDim.x + threadIdx.x;
    if (i >= NE9) return;
    int t = (int)(i / EE), e = (int)(i - (long)t * EE);
    int dst = EI[((size_t)t * 2 + 1) * EE + e];
    float ex = expf(g_AL[i] - g_AMAX[(size_t)t * NN + dst]);
    g_AL[i] = ex;
    atomicAdd(&g_DEN[(size_t)t * NN + dst], ex);
}

// warp per node: gathers all in-edges (all 9 types), accumulates
//   ACC[node] += sum_e w*V_t[src]  and  WNEA[node][t*32+c] = sum_e w*nea_t[e][c]
//   plus (sum_e w)*be_t per type present.
__global__ void __launch_bounds__(256) att_gather(const float* __restrict__ be_b)
{
    __shared__ float sW[8][NTT * EHH];
    __shared__ float sSW[8][NTT];
    __shared__ float sBE[NTT * DD];

    int tid = threadIdx.x;
    for (int j = tid; j < NTT * DD; j += 256) sBE[j] = be_b[j];

    int wrp = tid >> 5, lane = tid & 31;
    int node = blockIdx.x * 8 + wrp;
    for (int j = lane; j < NTT * EHH; j += 32) sW[wrp][j] = 0.f;
    if (lane < NTT) sSW[wrp][lane] = 0.f;
    __syncthreads();
    if (node >= NN) return;

    float acc[10];
    float* accp = g_ACC + (size_t)node * DD;
#pragma unroll
    for (int i = 0; i < 10; i++) acc[i] = accp[lane + 32 * i];

    int start = g_CNT[node], end = g_CNT[node + 1];
    for (int idx = start; idx < end; idx++) {
        int pe  = g_CSRE[idx];
        int src = g_CSRS[idx];
        int t = pe / EE;
        float w = g_AL[pe] / (g_DEN[(size_t)t * NN + node] + 1e-16f);
        const float* v = g_V + ((size_t)t * NN + src) * DD;
#pragma unroll
        for (int i = 0; i < 10; i++)
            acc[i] += w * v[lane + 32 * i];
        sW[wrp][t * EHH + lane] += w * g_NEA[(size_t)pe * EHH + lane];
        if (lane == 0) sSW[wrp][t] += w;
    }
    __syncwarp();

    // be contributions: (sum w) * be_t
#pragma unroll
    for (int t = 0; t < NTT; t++) {
        float swt = sSW[wrp][t];
        if (swt != 0.f) {
#pragma unroll
            for (int i = 0; i < 10; i++)
                acc[i] += swt * sBE[t * DD + lane + 32 * i];
        }
    }

#pragma unroll
    for (int i = 0; i < 10; i++) accp[lane + 32 * i] = acc[i];
    float* wn = g_WNEA + (size_t)node * (NTT * EHH);
#pragma unroll
    for (int t = 0; t < NTT; t++) wn[t * EHH + lane] = sW[wrp][t * EHH + lane];
}

// ---------------- norm / residual / pooling ----------------
__global__ void count_nodes(const int* __restrict__ batch)
{
    int i = blockIdx.x * blockDim.x + threadIdx.x;
    if (i < NN) atomicAdd(&g_GC[batch[i]], 1);
}

__global__ void gstats(const int* __restrict__ batch)
{
    int w = blockIdx.x * (blockDim.x / 32) + threadIdx.x / 32;
    int lane = threadIdx.x & 31;
    if (w >= NN) return;
    const float* a = g_ACC + (size_t)w * DD;
    float s1 = 0.f, s2 = 0.f;
#pragma unroll
    for (int c = lane; c < DD; c += 32) {
        float v = a[c] * (1.f / 9.f);
        v = v > 0.f ? v : 0.01f * v;
        s1 += v; s2 += v * v;
    }
#pragma unroll
    for (int off = 16; off; off >>= 1) {
        s1 += __shfl_xor_sync(0xffffffffu, s1, off);
        s2 += __shfl_xor_sync(0xffffffffu, s2, off);
    }
    if (lane == 0) {
        int g = batch[w];
        atomicAdd(&g_GS[g], s1);
        atomicAdd(&g_GQ[g], s2);
    }
}

__global__ void gfinal()
{
    int g = blockIdx.x * blockDim.x + threadIdx.x;
    if (g >= GG) return;
    float cnt  = (float)g_GC[g];
    float norm = fmaxf(cnt, 1.f) * (float)DD;
    float mean = g_GS[g] / norm;
    float var  = fmaxf(g_GQ[g] / norm - mean * mean, 0.f);
    g_MEAN[g] = mean;
    g_RSTD[g] = rsqrtf(var + 1e-5f);
}

__global__ void hupdate(const int* __restrict__ batch,
                        const float* __restrict__ gamma, const float* __restrict__ beta)
{
    size_t i = (size_t)blockIdx.x * blockDim.x + threadIdx.x;
    if (i >= (size_t)NN * DD) return;
    int node = (int)(i / DD), c = (int)(i % DD);
    int g = batch[node];
    float v = g_ACC[i] * (1.f / 9.f);
    v = v > 0.f ? v : 0.01f * v;
    float xn = (v - g_MEAN[g]) * g_RSTD[g] * gamma[c] + beta[c];
    g_H[i] = 0.5f * (g_H[i] + xn);
}

__device__ __forceinline__ unsigned fkey(float f)
{
    unsigned u = __float_as_uint(f);
    return (u & 0x80000000u) ? ~u : (u | 0x80000000u);
}
__device__ __forceinline__ float funkey(unsigned u)
{
    return (u & 0x80000000u) ? __uint_as_float(u & 0x7FFFFFFFu) : __uint_as_float(~u);
}

__global__ void maxred(const int* __restrict__ batch)
{
    size_t i = (size_t)blockIdx.x * blockDim.x + threadIdx.x;
    if (i >= (size_t)NN * DD) return;
    int node = (int)(i / DD), c = (int)(i % DD);
    atomicMax(&g_OUTU[(size_t)batch[node] * DD + c], fkey(g_H[i]));
}

__global__ void finalize(float* __restrict__ out)
{
    int i = blockIdx.x * blockDim.x + threadIdx.x;
    if (i < GG * DD) out[i] = funkey(g_OUTU[i]);
}

// ---------------- host orchestration ----------------
extern "C" void kernel_launch(void* const* d_in, const int* in_sizes, int n_in,
                              void* d_out, int out_size)
{
    const float* x     = (const float*)d_in[0];
    const int*   batch = (const int*)d_in[1];
    const int*   EI    = (const int*)d_in[2];
    const float* EA    = (const float*)d_in[3];
    const float* W1    = (const float*)d_in[4];
    const float* b1    = (const float*)d_in[5];
    const float* W2    = (const float*)d_in[6];
    const float* b2    = (const float*)d_in[7];
    const float* Wq    = (const float*)d_in[8];
    const float* bq    = (const float*)d_in[9];
    const float* Wk    = (const float*)d_in[10];
    const float* bk    = (const float*)d_in[11];
    const float* Wv    = (const float*)d_in[12];
    const float* bv    = (const float*)d_in[13];
    const float* We    = (const float*)d_in[14];
    const float* be    = (const float*)d_in[15];
    const float* Ws    = (const float*)d_in[16];
    const float* bs    = (const float*)d_in[17];
    const float* gamma = (const float*)d_in[18];
    const float* beta  = (const float*)d_in[19];
    float* out = (float*)d_out;

    float *pXS, *pXD, *pQ, *pK, *pV, *pQW, *pWNEA, *pACC, *pH, *pNEA;
    float *pGS, *pGQ, *pWSUM, *pBSUM, *pWET;
    int *pGC, *pCNT;
    unsigned *pOUTU;
    cudaGetSymbolAddress((void**)&pXS,   g_XS);
    cudaGetSymbolAddress((void**)&pXD,   g_XD);
    cudaGetSymbolAddress((void**)&pQ,    g_Q);
    cudaGetSymbolAddress((void**)&pK,    g_K);
    cudaGetSymbolAddress((void**)&pV,    g_V);
    cudaGetSymbolAddress((void**)&pQW,   g_QW);
    cudaGetSymbolAddress((void**)&pWNEA, g_WNEA);
    cudaGetSymbolAddress((void**)&pACC,  g_ACC);
    cudaGetSymbolAddress((void**)&pH,    g_H);
    cudaGetSymbolAddress((void**)&pNEA,  g_NEA);
    cudaGetSymbolAddress((void**)&pGS,   g_GS);
    cudaGetSymbolAddress((void**)&pGQ,   g_GQ);
    cudaGetSymbolAddress((void**)&pGC,   g_GC);
    cudaGetSymbolAddress((void**)&pCNT,  g_CNT);
    cudaGetSymbolAddress((void**)&pWSUM, g_WSUM);
    cudaGetSymbolAddress((void**)&pBSUM, g_BSUM);
    cudaGetSymbolAddress((void**)&pWET,  g_WET);
    cudaGetSymbolAddress((void**)&pOUTU, g_OUTU);

    const int MT_N128 = (NN + 127) / 128;   // 391
    const long NND = (long)NN * DD;

    // ---- preprocessing ----
    cudaMemsetAsync(pGC, 0, GG * sizeof(int));
    count_nodes<<<(NN + 255) / 256, 256>>>(batch);

    wsum_all<<<(NBB * DD * DD + NBB * DD + 255) / 256, 256>>>(Ws, bs);
    wet_all<<<(NBB * NTT * DD * EHH + 255) / 256, 256>>>(We);

    cudaMemsetAsync(pCNT, 0, (NN + 1) * sizeof(int));
    csr_count<<<(NE9 + 255) / 256, 256>>>(EI);
    csr_scan<<<1, 1024>>>();
    csr_fill<<<(NE9 + 255) / 256, 256>>>(EI);

    sgemm<<<dim3(1, MT_N128, 1), 256>>>(x, W1,                    nullptr, pXS, NN, DD, EHH, EHH, 0, 0, 0);
    sgemm<<<dim3(1, MT_N128, 1), 256>>>(x, W1 + (size_t)DD * EHH, nullptr, pXD, NN, DD, EHH, EHH, 0, 0, 0);
    edge_mlp<<<(NE9 + 7) / 8, 256>>>(EI, EA, W1, b1, W2, b2);

    cudaMemcpyAsync(pH, x, NND * sizeof(float), cudaMemcpyDeviceToDevice);

    for (int b = 0; b < NBB; b++) {
        // skip (folded over t): ACC = H @ WSUM_b + BSUM_b
        mma_gemm<false><<<dim3(5, MT_N128, 1), 256>>>(
            pH, pWSUM + (size_t)b * DD * DD, pBSUM + (size_t)b * DD, pACC,
            NN, DD, DD, DD, 0, 0, 0, 0);

        // batched Q/K/V over t (z=9)
        mma_gemm<false><<<dim3(5, MT_N128, NTT), 256>>>(
            pH, Wq + (size_t)b * NTT * DD * DD, bq + (size_t)b * NTT * DD, pQ,
            NN, DD, DD, DD, 0, (long)DD * DD, NND, DD);
        mma_gemm<false><<<dim3(5, MT_N128, NTT), 256>>>(
            pH, Wk + (size_t)b * NTT * DD * DD, bk + (size_t)b * NTT * DD, pK,
            NN, DD, DD, DD, 0, (long)DD * DD, NND, DD);
        mma_gemm<false><<<dim3(5, MT_N128, NTT), 256>>>(
            pH, Wv + (size_t)b * NTT * DD * DD, bv + (size_t)b * NTT * DD, pV,
            NN, DD, DD, DD, 0, (long)DD * DD, NND, DD);

        // QW_t = Q_t @ We_t^T   (z=9, Nout=32)
        sgemm<<<dim3(1, MT_N128, NTT), 256>>>(
            pQ, pWET + (size_t)b * NTT * DD * EHH, nullptr, pQW,
            NN, DD, EHH, EHH, NND, (long)DD * EHH, (long)NN * EHH);

        fill_amax_den<<<(NTT * NN + 255) / 256, 256>>>();
        att_pass1<<<(NE9 + 7) / 8, 256>>>(EI);
        att_pass2<<<(NE9 + 255) / 256, 256>>>(EI);
        att_gather<<<(NN + 7) / 8, 256>>>(be + (size_t)b * NTT * DD);

        // ACC += WNEA @ [stacked We_t]  (K = 9*32 = 288)
        mma_gemm<true><<<dim3(5, MT_N128, 1), 256>>>(
            pWNEA, We + (size_t)b * NTT * EHH * DD, nullptr, pACC,
            NN, NTT * EHH, DD, DD, 0, 0, 0, 0);

        cudaMemsetAsync(pGS, 0, GG * sizeof(float));
        cudaMemsetAsync(pGQ, 0, GG * sizeof(float));
        gstats<<<(NN + 7) / 8, 256>>>(batch);
        gfinal<<<1, 256>>>();
        hupdate<<<(unsigned)((NND + 255) / 256), 256>>>(batch,
                                                        gamma + (size_t)b * DD,
                                                        beta  + (size_t)b * DD);
    }

    cudaMemsetAsync(pOUTU, 0, (size_t)GG * DD * sizeof(unsigned));
    maxred<<<(unsigned)((NND + 255) / 256), 256>>>(batch);
    finalize<<<(GG * DD + 255) / 256, 256>>>(out);
}